// round 15
// baseline (speedup 1.0000x reference)
#include <cuda_runtime.h>
#include <cuda_fp16.h>
#include <stdint.h>

#define N_NODES 50000
#define N_EDGES 800000
#define D 96
#define DC 24              // D / 4 (float4 chunks per row)
#define XS_STRIDE 25       // padded row stride in float4
#define GEMM_ROWS 128      // rows per block
#define GEMM_THREADS 192   // 12 col-groups x 16 row-groups
#define GEMM_SMEM ((D * DC + GEMM_ROWS * XS_STRIDE) * 16)  // Ws + Xs bytes

// Scratch (device globals; no allocation allowed)
__device__ int    g_is64;
__device__ float  g_deg[N_NODES];
__device__ __half g_h[(size_t)N_NODES * D];    // h * dinv[row], fp16

// packed f32x2 helpers (sm_103a FFMA2 — PTX only)
__device__ __forceinline__ unsigned long long pack2(float x, float y) {
    unsigned long long p;
    asm("mov.b64 %0, {%1, %2};" : "=l"(p) : "f"(x), "f"(y));
    return p;
}
__device__ __forceinline__ void fma2(unsigned long long& acc,
                                     unsigned long long a,
                                     unsigned long long b) {
    asm("fma.rn.f32x2 %0, %1, %2, %0;" : "+l"(acc) : "l"(a), "l"(b));
}
__device__ __forceinline__ void unpack2(unsigned long long p, float& x, float& y) {
    asm("mov.b64 {%0, %1}, %2;" : "=f"(x), "=f"(y) : "l"(p));
}

// ---------------------------------------------------------------------------
// 1. init: deg = 1 (self loop weight); thread 0 detects edge_index dtype.
//    int64 values < 2^31 have all-zero odd int32 words; random int32 ids don't.
// ---------------------------------------------------------------------------
__global__ void init_kernel(const int* __restrict__ ei32) {
    int i = blockIdx.x * blockDim.x + threadIdx.x;
    if (i < N_NODES) g_deg[i] = 1.0f;
    if (i == 0) {
        int looks64 = 1, any_nonzero = 0;
        #pragma unroll
        for (int k = 0; k < 64; k++) {
            if (ei32[2 * k + 1] != 0) looks64 = 0;
            if (ei32[2 * k] != 0) any_nonzero = 1;
        }
        g_is64 = (looks64 && any_nonzero) ? 1 : 0;
    }
}

// ---------------------------------------------------------------------------
// 2. deg[col] += ew
// ---------------------------------------------------------------------------
__global__ void accum_deg_kernel(const void* __restrict__ ei,
                                 const float* __restrict__ ew) {
    int e = blockIdx.x * blockDim.x + threadIdx.x;
    if (e < N_EDGES) {
        int is64 = g_is64;
        int col = is64 ? (int)((const long long*)ei)[(size_t)N_EDGES + e]
                       : ((const int*)ei)[(size_t)N_EDGES + e];
        atomicAdd(&g_deg[col], ew[e]);
    }
}

// ---------------------------------------------------------------------------
// 3. GEMM + epilogue:  h' = (x @ W) * dinv[row]  -> g_h (fp16)
//                      out[row] = b + h' * dinv[row]   (fp32, self loop + bias)
//    8x8 thread tiles, FFMA2 inner loop, 88KB dynamic smem.
// ---------------------------------------------------------------------------
__global__ __launch_bounds__(GEMM_THREADS)
void gemm_kernel(const float* __restrict__ x, const float* __restrict__ W,
                 const float* __restrict__ b, float* __restrict__ out) {
    extern __shared__ float smem[];
    float4* Ws4 = (float4*)smem;                       // [D][DC]
    float4* Xs4 = (float4*)(smem + D * D);             // [GEMM_ROWS][XS_STRIDE]

    int tid = threadIdx.x;
    int row0 = blockIdx.x * GEMM_ROWS;

    const float4* W4 = (const float4*)W;
    #pragma unroll
    for (int i = tid; i < D * DC; i += GEMM_THREADS) Ws4[i] = W4[i];

    const float4* X4 = (const float4*)x;
    #pragma unroll
    for (int i = tid; i < GEMM_ROWS * DC; i += GEMM_THREADS) {
        int r = i / DC;
        int c = i - r * DC;
        int gr = row0 + r;
        Xs4[r * XS_STRIDE + c] = (gr < N_NODES) ? X4[(size_t)gr * DC + c]
                                                : make_float4(0.f, 0.f, 0.f, 0.f);
    }
    __syncthreads();

    int tx = tid % 12;       // col group: float4 chunks 2*tx, 2*tx+1
    int ty = tid / 12;       // row group 0..15
    int rbase = ty * 8;
    int c0 = 2 * tx, c1 = 2 * tx + 1;

    unsigned long long acc[8][4];
    #pragma unroll
    for (int r = 0; r < 8; r++)
        #pragma unroll
        for (int q = 0; q < 4; q++) acc[r][q] = 0ull;

    #pragma unroll 2
    for (int kc = 0; kc < DC; kc++) {
        float4 xv[8];
        #pragma unroll
        for (int r = 0; r < 8; r++) xv[r] = Xs4[(rbase + r) * XS_STRIDE + kc];
        #pragma unroll
        for (int kk = 0; kk < 4; kk++) {
            float4 wv0 = Ws4[(kc * 4 + kk) * DC + c0];
            float4 wv1 = Ws4[(kc * 4 + kk) * DC + c1];
            unsigned long long w0XY = pack2(wv0.x, wv0.y);
            unsigned long long w0ZW = pack2(wv0.z, wv0.w);
            unsigned long long w1XY = pack2(wv1.x, wv1.y);
            unsigned long long w1ZW = pack2(wv1.z, wv1.w);
            #pragma unroll
            for (int r = 0; r < 8; r++) {
                float a = ((const float*)&xv[r])[kk];
                unsigned long long aa = pack2(a, a);
                fma2(acc[r][0], aa, w0XY);
                fma2(acc[r][1], aa, w0ZW);
                fma2(acc[r][2], aa, w1XY);
                fma2(acc[r][3], aa, w1ZW);
            }
        }
    }

    float4 bv0 = ((const float4*)b)[c0];
    float4 bv1 = ((const float4*)b)[c1];
    uint4* H4h = (uint4*)g_h;           // one uint4 = 8 halves = chunk pair
    float4* O4 = (float4*)out;
    #pragma unroll
    for (int r = 0; r < 8; r++) {
        int gr = row0 + rbase + r;
        if (gr < N_NODES) {
            float s = rsqrtf(g_deg[gr]);
            float4 h0, h1;
            unpack2(acc[r][0], h0.x, h0.y);
            unpack2(acc[r][1], h0.z, h0.w);
            unpack2(acc[r][2], h1.x, h1.y);
            unpack2(acc[r][3], h1.z, h1.w);
            h0.x *= s; h0.y *= s; h0.z *= s; h0.w *= s;
            h1.x *= s; h1.y *= s; h1.z *= s; h1.w *= s;
            // fp16 store of chunk pair (one STG.128); out stays fp32
            __half2 p00 = __floats2half2_rn(h0.x, h0.y);
            __half2 p01 = __floats2half2_rn(h0.z, h0.w);
            __half2 p10 = __floats2half2_rn(h1.x, h1.y);
            __half2 p11 = __floats2half2_rn(h1.z, h1.w);
            uint4 v;
            v.x = *(uint32_t*)&p00; v.y = *(uint32_t*)&p01;
            v.z = *(uint32_t*)&p10; v.w = *(uint32_t*)&p11;
            H4h[(size_t)gr * 12 + tx] = v;
            float4 o0, o1;   // b + h*dinv^2 (fp32 path)
            o0.x = bv0.x + h0.x * s; o0.y = bv0.y + h0.y * s;
            o0.z = bv0.z + h0.z * s; o0.w = bv0.w + h0.w * s;
            o1.x = bv1.x + h1.x * s; o1.y = bv1.y + h1.y * s;
            o1.z = bv1.z + h1.z * s; o1.w = bv1.w + h1.w * s;
            O4[(size_t)gr * DC + c0] = o0;
            O4[(size_t)gr * DC + c1] = o1;
        }
    }
}

// ---------------------------------------------------------------------------
// 4. Scatter: 12 threads per edge, 8 floats (one uint4 of fp16 h') each.
//    Block = 288 threads = exactly 24 edges; tid/12 via multiply-shift.
//    out[col*96 + 8c .. +8) += h'[row] * (ew*rsqrt(deg[col]))  via 2x red.v4
// ---------------------------------------------------------------------------
__global__ __launch_bounds__(288)
void scatter_kernel(const void* __restrict__ ei,
                    const float* __restrict__ ew,
                    float* __restrict__ out) {
    int tid = threadIdx.x;
    int e_local = (tid * 5462) >> 16;      // tid / 12 for tid < 288
    int c = tid - e_local * 12;            // chunk-pair index 0..11
    int e = blockIdx.x * 24 + e_local;
    if (e >= N_EDGES) return;

    int is64 = g_is64;
    int row, col;
    if (is64) {
        row = (int)((const long long*)ei)[e];
        col = (int)((const long long*)ei)[(size_t)N_EDGES + e];
    } else {
        row = ((const int*)ei)[e];
        col = ((const int*)ei)[(size_t)N_EDGES + e];
    }
    float nrm = ew[e] * rsqrtf(g_deg[col]);

    uint4 hv = ((const uint4*)g_h)[(size_t)row * 12 + c];   // 8 halves
    float2 f0 = __half22float2(*(__half2*)&hv.x);
    float2 f1 = __half22float2(*(__half2*)&hv.y);
    float2 f2 = __half22float2(*(__half2*)&hv.z);
    float2 f3 = __half22float2(*(__half2*)&hv.w);

    float* base = out + (size_t)col * D + c * 8;
    float a0 = f0.x * nrm, a1 = f0.y * nrm, a2 = f1.x * nrm, a3 = f1.y * nrm;
    asm volatile("red.global.add.v4.f32 [%0], {%1, %2, %3, %4};"
                 :: "l"(base), "f"(a0), "f"(a1), "f"(a2), "f"(a3)
                 : "memory");
    float b0 = f2.x * nrm, b1 = f2.y * nrm, b2 = f3.x * nrm, b3 = f3.y * nrm;
    asm volatile("red.global.add.v4.f32 [%0], {%1, %2, %3, %4};"
                 :: "l"(base + 4), "f"(b0), "f"(b1), "f"(b2), "f"(b3)
                 : "memory");
}

// ---------------------------------------------------------------------------
// Launch.  Inputs: x[N*96] f32, edge_index[2*E] int32/int64, edge_weight[E] f32,
//                  W[96*96] f32, b[96] f32.  Output: [N*96] f32.
// ---------------------------------------------------------------------------
extern "C" void kernel_launch(void* const* d_in, const int* in_sizes, int n_in,
                              void* d_out, int out_size) {
    const float* x = (const float*)d_in[0];
    const void* ei = d_in[1];
    const float* ew = (const float*)d_in[2];
    const float* W = (const float*)d_in[3];
    const float* b = (const float*)d_in[4];
    float* out = (float*)d_out;

    static int smem_set = 0;
    if (!smem_set) {
        cudaFuncSetAttribute(gemm_kernel,
                             cudaFuncAttributeMaxDynamicSharedMemorySize,
                             GEMM_SMEM);
        smem_set = 1;
    }

    init_kernel<<<(N_NODES + 255) / 256, 256>>>((const int*)ei);
    accum_deg_kernel<<<(N_EDGES + 255) / 256, 256>>>(ei, ew);
    gemm_kernel<<<(N_NODES + GEMM_ROWS - 1) / GEMM_ROWS, GEMM_THREADS, GEMM_SMEM>>>(x, W, b, out);
    scatter_kernel<<<(N_EDGES + 23) / 24, 288>>>(ei, ew, out);
}

// round 16
// speedup vs baseline: 1.1711x; 1.1711x over previous
#include <cuda_runtime.h>
#include <cuda_fp16.h>
#include <stdint.h>

#define N_NODES 50000
#define N_EDGES 800000
#define D 96
#define DC 24              // D / 4 (float4 chunks per row)

// ---- HMMA GEMM geometry ----
#define GROWS 64           // M rows per block
#define GTHREADS 128       // 4 warps, each owns one m16 tile
#define KP 48              // K in half2 pairs
#define AST 50             // A row stride in u32 (100 halves, bank-decorrelated)
#define NT 12              // N tiles of 8
#define KT 6               // K tiles of 16
// smem (u32 units): A_hi[64*50] A_lo[64*50] B_hi[96*50] B_lo[96*50]
#define SM_AH 0
#define SM_AL 3200
#define SM_BH 6400
#define SM_BL 11200
#define GEMM_SMEM (16000 * 4)   // 64000 B

// Scratch (device globals; no allocation allowed)
__device__ int      g_is64;
__device__ float    g_deg[N_NODES];
__device__ __half   g_h[(size_t)N_NODES * D];  // h * dinv[row], fp16
__device__ unsigned short gWh[D * 100];        // W^T fp16 hi, [n][k] padded
__device__ unsigned short gWl[D * 100];        // W^T fp16 lo

// ---------------------------------------------------------------------------
// 1. init: deg = 1; detect edge_index dtype; split W -> transposed fp16 hi/lo
// ---------------------------------------------------------------------------
__global__ void init_kernel(const int* __restrict__ ei32,
                            const float* __restrict__ W) {
    int i = blockIdx.x * blockDim.x + threadIdx.x;
    if (i < N_NODES) g_deg[i] = 1.0f;
    if (i < D * D) {
        int k = i / D, n = i - k * D;     // W[k][n], coalesced over n
        float w = W[i];
        __half h = __float2half_rn(w);
        __half l = __float2half_rn(w - __half2float(h));
        gWh[n * 100 + k] = __half_as_ushort(h);
        gWl[n * 100 + k] = __half_as_ushort(l);
    }
    if (i == 0) {
        int looks64 = 1, any_nonzero = 0;
        #pragma unroll
        for (int k = 0; k < 64; k++) {
            if (ei32[2 * k + 1] != 0) looks64 = 0;
            if (ei32[2 * k] != 0) any_nonzero = 1;
        }
        g_is64 = (looks64 && any_nonzero) ? 1 : 0;
    }
}

// ---------------------------------------------------------------------------
// 2. deg[col] += ew
// ---------------------------------------------------------------------------
__global__ void accum_deg_kernel(const void* __restrict__ ei,
                                 const float* __restrict__ ew) {
    int e = blockIdx.x * blockDim.x + threadIdx.x;
    if (e < N_EDGES) {
        int is64 = g_is64;
        int col = is64 ? (int)((const long long*)ei)[(size_t)N_EDGES + e]
                       : ((const int*)ei)[(size_t)N_EDGES + e];
        atomicAdd(&g_deg[col], ew[e]);
    }
}

// ---------------------------------------------------------------------------
// 3. HMMA GEMM + epilogue: D = x@W via fp16 hi/lo (3 passes, fp32 acc)
//    h' = D * dinv -> g_h (fp16);  out = b + D * dinv^2  (fp32)
// ---------------------------------------------------------------------------
__device__ __forceinline__ void mma16816(float* c, uint32_t a0, uint32_t a1,
                                         uint32_t a2, uint32_t a3,
                                         uint32_t b0, uint32_t b1) {
    asm volatile(
        "mma.sync.aligned.m16n8k16.row.col.f32.f16.f16.f32 "
        "{%0,%1,%2,%3}, {%4,%5,%6,%7}, {%8,%9}, {%0,%1,%2,%3};"
        : "+f"(c[0]), "+f"(c[1]), "+f"(c[2]), "+f"(c[3])
        : "r"(a0), "r"(a1), "r"(a2), "r"(a3), "r"(b0), "r"(b1));
}

__global__ __launch_bounds__(GTHREADS)
void gemm_kernel(const float* __restrict__ x, const float* __restrict__ b,
                 float* __restrict__ out) {
    extern __shared__ uint32_t sm[];
    int tid = threadIdx.x;
    int row0 = blockIdx.x * GROWS;

    // A fill: x rows -> fp16 hi/lo pairs, padded stride
    const float2* X2 = (const float2*)x;
    for (int i = tid; i < GROWS * KP; i += GTHREADS) {
        int r = i / KP, kp = i - r * KP;
        int gr = row0 + r;
        float2 xv = make_float2(0.f, 0.f);
        if (gr < N_NODES) xv = X2[(size_t)gr * KP + kp];
        __half h0 = __float2half_rn(xv.x);
        __half h1 = __float2half_rn(xv.y);
        __half l0 = __float2half_rn(xv.x - __half2float(h0));
        __half l1 = __float2half_rn(xv.y - __half2float(h1));
        sm[SM_AH + r * AST + kp] =
            (uint32_t)__half_as_ushort(h0) | ((uint32_t)__half_as_ushort(h1) << 16);
        sm[SM_AL + r * AST + kp] =
            (uint32_t)__half_as_ushort(l0) | ((uint32_t)__half_as_ushort(l1) << 16);
    }
    // B fill: copy pre-split W^T (u32 coalesced)
    const uint32_t* WH = (const uint32_t*)gWh;
    const uint32_t* WL = (const uint32_t*)gWl;
    for (int i = tid; i < D * AST; i += GTHREADS) {
        sm[SM_BH + i] = WH[i];
        sm[SM_BL + i] = WL[i];
    }
    __syncthreads();

    int wid = tid >> 5, lane = tid & 31;
    int q = lane & 3, rq = lane >> 2;
    int mrow = wid * 16;

    float acc[NT][4];
    #pragma unroll
    for (int nt = 0; nt < NT; nt++)
        #pragma unroll
        for (int j = 0; j < 4; j++) acc[nt][j] = 0.f;

    const int aoff[3] = {SM_AH, SM_AH, SM_AL};
    const int boff[3] = {SM_BH, SM_BL, SM_BH};
    #pragma unroll
    for (int p = 0; p < 3; p++) {
        const uint32_t* A = sm + aoff[p];
        const uint32_t* Bm = sm + boff[p];
        #pragma unroll
        for (int t = 0; t < KT; t++) {
            int ka = 8 * t + q;
            uint32_t a0 = A[(mrow + rq) * AST + ka];
            uint32_t a1 = A[(mrow + rq + 8) * AST + ka];
            uint32_t a2 = A[(mrow + rq) * AST + ka + 4];
            uint32_t a3 = A[(mrow + rq + 8) * AST + ka + 4];
            #pragma unroll
            for (int nt = 0; nt < NT; nt++) {
                int n = nt * 8 + rq;
                uint32_t b0 = Bm[n * AST + ka];
                uint32_t b1 = Bm[n * AST + ka + 4];
                mma16816(acc[nt], a0, a1, a2, a3, b0, b1);
            }
        }
    }

    // Epilogue: lane owns rows (mrow+rq, mrow+rq+8), col pairs nt*8 + q*2
    int r0g = row0 + mrow + rq;
    int r1g = r0g + 8;
    float s0 = (r0g < N_NODES) ? rsqrtf(g_deg[r0g]) : 0.f;
    float s1 = (r1g < N_NODES) ? rsqrtf(g_deg[r1g]) : 0.f;
    uint32_t* Hu = (uint32_t*)g_h;
    float2* O2 = (float2*)out;
    const float2* B2 = (const float2*)b;
    #pragma unroll
    for (int nt = 0; nt < NT; nt++) {
        int ci = nt * 4 + q;            // half2 / float2 column index
        float2 bv = B2[ci];
        if (r0g < N_NODES) {
            float h0 = acc[nt][0] * s0, h1 = acc[nt][1] * s0;
            __half2 p = __floats2half2_rn(h0, h1);
            Hu[(size_t)r0g * 48 + ci] = *(uint32_t*)&p;
            O2[(size_t)r0g * 48 + ci] = make_float2(bv.x + h0 * s0, bv.y + h1 * s0);
        }
        if (r1g < N_NODES) {
            float h0 = acc[nt][2] * s1, h1 = acc[nt][3] * s1;
            __half2 p = __floats2half2_rn(h0, h1);
            Hu[(size_t)r1g * 48 + ci] = *(uint32_t*)&p;
            O2[(size_t)r1g * 48 + ci] = make_float2(bv.x + h0 * s1, bv.y + h1 * s1);
        }
    }
}

// ---------------------------------------------------------------------------
// 4. Scatter (exact R14): thread t -> edge t/24, chunk t%24; fp16 h' gather,
//    fp32 vector red into out.
// ---------------------------------------------------------------------------
__global__ __launch_bounds__(256)
void scatter_kernel(const void* __restrict__ ei,
                    const float* __restrict__ ew,
                    float* __restrict__ out) {
    int idx = blockIdx.x * blockDim.x + threadIdx.x;
    if (idx >= N_EDGES * DC) return;
    int e = idx / DC;
    int c = idx - e * DC;
    int is64 = g_is64;
    int row, col;
    if (is64) {
        row = (int)((const long long*)ei)[e];
        col = (int)((const long long*)ei)[(size_t)N_EDGES + e];
    } else {
        row = ((const int*)ei)[e];
        col = ((const int*)ei)[(size_t)N_EDGES + e];
    }
    float nrm = ew[e] * rsqrtf(g_deg[col]);

    uint2 hv = ((const uint2*)g_h)[(size_t)row * DC + c];
    float2 f0 = __half22float2(*(__half2*)&hv.x);
    float2 f1 = __half22float2(*(__half2*)&hv.y);

    float mx = f0.x * nrm, my = f0.y * nrm, mz = f1.x * nrm, mw = f1.y * nrm;
    float* addr = out + (size_t)col * D + c * 4;
    asm volatile("red.global.add.v4.f32 [%0], {%1, %2, %3, %4};"
                 :: "l"(addr), "f"(mx), "f"(my), "f"(mz), "f"(mw)
                 : "memory");
}

// ---------------------------------------------------------------------------
// Launch.  Inputs: x[N*96] f32, edge_index[2*E] int32/int64, edge_weight[E] f32,
//                  W[96*96] f32, b[96] f32.  Output: [N*96] f32.
// ---------------------------------------------------------------------------
extern "C" void kernel_launch(void* const* d_in, const int* in_sizes, int n_in,
                              void* d_out, int out_size) {
    const float* x = (const float*)d_in[0];
    const void* ei = d_in[1];
    const float* ew = (const float*)d_in[2];
    const float* W = (const float*)d_in[3];
    const float* b = (const float*)d_in[4];
    float* out = (float*)d_out;

    static int smem_set = 0;
    if (!smem_set) {
        cudaFuncSetAttribute(gemm_kernel,
                             cudaFuncAttributeMaxDynamicSharedMemorySize,
                             GEMM_SMEM);
        smem_set = 1;
    }

    init_kernel<<<(N_NODES + 255) / 256, 256>>>((const int*)ei, W);
    accum_deg_kernel<<<(N_EDGES + 255) / 256, 256>>>(ei, ew);
    gemm_kernel<<<(N_NODES + GROWS - 1) / GROWS, GTHREADS, GEMM_SMEM>>>(x, b, out);
    scatter_kernel<<<(N_EDGES * DC + 255) / 256, 256>>>(ei, ew, out);
}